// round 10
// baseline (speedup 1.0000x reference)
#include <cuda_runtime.h>
#include <cuda_fp16.h>
#include <cstdint>

// Problem constants
#define NN 100000      // nodes
#define NE 3200000     // edges
#define NF 512         // in features
#define NH 256         // hidden
#define NL 64          // latent

// ---------------------------------------------------------------------------
// Scratch (device globals -> allocation-free, graph-capturable)
// ---------------------------------------------------------------------------
__device__ __half g_xwh[(size_t)NN * NH];   // GEMM1 out [NN,256]
__device__ __half g_h  [(size_t)NN * NH];   // relu(spmm1) fp16 [NN,256]
__device__ __half g_z  [(size_t)NN * 128];  // GEMM2 out [NN,128]
__device__ __half g_B1 [(size_t)256 * 512]; // W1^T fp16  [N=256, K=512]
__device__ __half g_B2 [(size_t)128 * 256]; // [Wmu|Wlv]^T fp16 [N=128, K=256]
__device__ int   g_off[NN + 1];
__device__ int   g_deg[NN];
__device__ int   g_cur[NN];
__device__ int2  g_edge[NE];                // .x = src, .y = bits(weight), sorted by dst

// ---------------------------------------------------------------------------
// Streams/events for graph-forked overlap (created at load time)
// ---------------------------------------------------------------------------
struct OverlapRes {
    cudaStream_t s2 = nullptr;
    cudaEvent_t  eFork = nullptr, eJoin = nullptr;
    bool ok = false;
    OverlapRes() {
        ok = (cudaStreamCreateWithFlags(&s2, cudaStreamNonBlocking) == cudaSuccess) &&
             (cudaEventCreateWithFlags(&eFork, cudaEventDisableTiming) == cudaSuccess) &&
             (cudaEventCreateWithFlags(&eJoin, cudaEventDisableTiming) == cudaSuccess);
    }
};
static OverlapRes g_ov;

// ---------------------------------------------------------------------------
// PTX helpers
// ---------------------------------------------------------------------------
__device__ __forceinline__ uint32_t smem_u32(const void* p) {
    uint32_t a;
    asm("{ .reg .u64 t; cvta.to.shared.u64 t, %1; cvt.u32.u64 %0, t; }" : "=r"(a) : "l"(p));
    return a;
}
__device__ __forceinline__ void cp16(uint32_t dst, const void* src, int sz) {
    asm volatile("cp.async.cg.shared.global [%0], [%1], 16, %2;"
                 :: "r"(dst), "l"(src), "r"(sz) : "memory");
}
__device__ __forceinline__ void cp_commit() {
    asm volatile("cp.async.commit_group;" ::: "memory");
}
template<int N> __device__ __forceinline__ void cp_wait() {
    asm volatile("cp.async.wait_group %0;" :: "n"(N) : "memory");
}

// ---------------------------------------------------------------------------
// CSR build
// ---------------------------------------------------------------------------
__global__ void k_zero_deg() {
    int i = blockIdx.x * blockDim.x + threadIdx.x;
    if (i < NN) g_deg[i] = 0;
}
__global__ void k_hist(const int* __restrict__ ei) {
    int e = blockIdx.x * blockDim.x + threadIdx.x;
    if (e < NE) atomicAdd(&g_deg[__ldg(ei + NE + e)], 1);
}
__global__ void k_scan() {
    __shared__ int wsum[32];
    int tid = threadIdx.x, lane = tid & 31, wid = tid >> 5;
    int carry = 0;
    for (int base = 0; base < NN; base += 1024) {
        int i = base + tid;
        int v = (i < NN) ? g_deg[i] : 0;
        int x = v;
        #pragma unroll
        for (int o = 1; o < 32; o <<= 1) {
            int y = __shfl_up_sync(0xffffffffu, x, o);
            if (lane >= o) x += y;
        }
        if (lane == 31) wsum[wid] = x;
        __syncthreads();
        if (wid == 0) {
            int s = wsum[lane];
            #pragma unroll
            for (int o = 1; o < 32; o <<= 1) {
                int y = __shfl_up_sync(0xffffffffu, s, o);
                if (lane >= o) s += y;
            }
            wsum[lane] = s;
        }
        __syncthreads();
        int excl = carry + x - v + (wid ? wsum[wid - 1] : 0);
        if (i < NN) { g_off[i] = excl; g_cur[i] = excl; }
        carry += wsum[31];
        __syncthreads();
    }
    if (tid == 0) g_off[NN] = carry;
}
__global__ void k_scatter(const int* __restrict__ ei, const float* __restrict__ ew) {
    int e = blockIdx.x * blockDim.x + threadIdx.x;
    if (e < NE) {
        int src = __ldg(ei + e);
        int dst = __ldg(ei + NE + e);
        float w = __ldg(ew + e);
        int pos = atomicAdd(&g_cur[dst], 1);
        g_edge[pos] = make_int2(src, __float_as_int(w));
    }
}

// ---------------------------------------------------------------------------
// Weight prep (fp16)
// ---------------------------------------------------------------------------
__global__ __launch_bounds__(256) void k_prepB1(const float* __restrict__ W1) {
    int t = blockIdx.x * blockDim.x + threadIdx.x;
    if (t >= 256 * 512) return;
    int n = t >> 9, k = t & 511;
    g_B1[t] = __float2half_rn(W1[(size_t)k * 256 + n]);
}
__global__ __launch_bounds__(256) void k_prepB2(const float* __restrict__ Wmu,
                                                const float* __restrict__ Wlv) {
    int t = blockIdx.x * blockDim.x + threadIdx.x;
    if (t >= 128 * 256) return;
    int n = t >> 8, k = t & 255;
    float w = (n < 64) ? Wmu[(size_t)k * 64 + n] : Wlv[(size_t)k * 64 + (n - 64)];
    g_B2[t] = __float2half_rn(w);
}

// ---------------------------------------------------------------------------
// GEMM1 with in-smem f32->fp16 conversion of A.
//   A: [M, KA] f32 row-major (cp.async -> smem f32, convert -> smem fp16)
//   B: [N, KA] fp16 K-contig (cp.async double-buffered)
//   Dynamic smem: A32[2][128*36] f32 | Ah[128*40] half | Bs[2][128*40] half
// ---------------------------------------------------------------------------
#define LDS32A 36
#define A32_BYTES (2 * 128 * LDS32A * 4)     // 36864
#define AH_OFF    A32_BYTES                  // 36864
#define AH_BYTES  (128 * 40 * 2)             // 10240
#define BS_OFF    (AH_OFF + AH_BYTES)        // 47104
#define BS_BYTES  (2 * 128 * 40 * 2)         // 20480
#define G1_SMEM   (BS_OFF + BS_BYTES)        // 67584

template<int CCH, int KA, int LDC>
__global__ __launch_bounds__(256) void k_mma1(const float* __restrict__ A,
                                              const __half* __restrict__ B,
                                              __half* __restrict__ C, int M)
{
    constexpr int LDS = 40;
    extern __shared__ char dsm[];
    float*  A32 = (float*)dsm;
    __half* Ah  = (__half*)(dsm + AH_OFF);

    int tid = threadIdx.x, lane = tid & 31, wid = tid >> 5;
    int m0 = blockIdx.y * 128, n0 = blockIdx.x * 128;
    int wm = (wid >> 2) * 64, wn = (wid & 3) * 32;

    float acc[4][4][4];
    #pragma unroll
    for (int a = 0; a < 4; a++)
        #pragma unroll
        for (int b = 0; b < 4; b++)
            #pragma unroll
            for (int q = 0; q < 4; q++) acc[a][b][q] = 0.f;

    uint32_t a32Base = smem_u32(dsm);
    uint32_t ahBase  = a32Base + AH_OFF;
    uint32_t bsBase  = a32Base + BS_OFF;

    int ar  = tid >> 1;              // 0..127 (row)
    int acz = (tid & 1) * 16;        // f32 col offset (0 or 16)
    int bs0 = (tid & 1) * 2;         // B cp16 slot
    int aok = (m0 + ar < M) ? 16 : 0;
    const float* ApBase = A + (size_t)(m0 + ar) * KA + acz;
    const __half* BpBase = B + (size_t)(n0 + ar) * KA;

    auto ldA = [&](int c, int st) {
        const float* Ap = ApBase + c * 32;
        uint32_t ad = a32Base + (uint32_t)(st * (128 * LDS32A) + ar * LDS32A + acz) * 4;
        #pragma unroll
        for (int i = 0; i < 4; i++)
            cp16(ad + i * 16, Ap + i * 4, aok);
    };
    auto ldB = [&](int c, int st) {
        const __half* Bp = BpBase + c * 32;
        uint32_t bd = bsBase + (uint32_t)(st * (128 * LDS) + ar * LDS) * 2;
        #pragma unroll
        for (int i = 0; i < 2; i++) {
            int s = bs0 + i;
            cp16(bd + s * 16, Bp + s * 8, 16);
        }
    };
    auto convertA = [&](int st) {
        const float* src = A32 + st * (128 * LDS32A) + ar * LDS32A + acz;
        __half2 h[8];
        #pragma unroll
        for (int i = 0; i < 4; i++) {
            float4 v = *(const float4*)(src + i * 4);
            h[2*i]   = __float22half2_rn(make_float2(v.x, v.y));
            h[2*i+1] = __float22half2_rn(make_float2(v.z, v.w));
        }
        uint4* dst = (uint4*)(Ah + ar * LDS + acz);
        dst[0] = ((uint4*)h)[0];
        dst[1] = ((uint4*)h)[1];
    };

    ldA(0, 0); ldB(0, 0); cp_commit();

    for (int c = 0; c < CCH; c++) {
        int st = c & 1;
        if (c + 1 < CCH) {
            ldA(c + 1, st ^ 1); ldB(c + 1, st ^ 1); cp_commit();
            cp_wait<1>();
        } else {
            cp_wait<0>();
        }
        __syncthreads();
        convertA(st);
        __syncthreads();

        #pragma unroll
        for (int ks = 0; ks < 2; ks++) {
            uint32_t ra[4][4], rb[4][2];
            #pragma unroll
            for (int mi = 0; mi < 4; mi++) {
                int row = wm + mi * 16 + (lane & 15);
                int col = ks * 16 + (lane >> 4) * 8;
                uint32_t ad = ahBase + (uint32_t)(row * LDS + col) * 2;
                asm volatile("ldmatrix.sync.aligned.m8n8.x4.shared.b16 {%0,%1,%2,%3}, [%4];"
                    : "=r"(ra[mi][0]), "=r"(ra[mi][1]), "=r"(ra[mi][2]), "=r"(ra[mi][3])
                    : "r"(ad));
            }
            #pragma unroll
            for (int ni = 0; ni < 4; ni++) {
                int row = wn + ni * 8 + (lane & 7);
                int col = ks * 16 + ((lane >> 3) & 1) * 8;
                uint32_t bd = bsBase + (uint32_t)(st * 128 * LDS + row * LDS + col) * 2;
                asm volatile("ldmatrix.sync.aligned.m8n8.x2.shared.b16 {%0,%1}, [%2];"
                    : "=r"(rb[ni][0]), "=r"(rb[ni][1]) : "r"(bd));
            }
            #pragma unroll
            for (int mi = 0; mi < 4; mi++)
                #pragma unroll
                for (int ni = 0; ni < 4; ni++)
                    asm volatile(
                        "mma.sync.aligned.m16n8k16.row.col.f32.f16.f16.f32 "
                        "{%0,%1,%2,%3}, {%4,%5,%6,%7}, {%8,%9}, {%0,%1,%2,%3};"
                        : "+f"(acc[mi][ni][0]), "+f"(acc[mi][ni][1]),
                          "+f"(acc[mi][ni][2]), "+f"(acc[mi][ni][3])
                        : "r"(ra[mi][0]), "r"(ra[mi][1]), "r"(ra[mi][2]), "r"(ra[mi][3]),
                          "r"(rb[ni][0]), "r"(rb[ni][1]));
        }
        __syncthreads();
    }

    #pragma unroll
    for (int mi = 0; mi < 4; mi++) {
        int r0 = m0 + wm + mi * 16 + (lane >> 2);
        #pragma unroll
        for (int ni = 0; ni < 4; ni++) {
            int cc = n0 + wn + ni * 8 + (lane & 3) * 2;
            if (r0 < M)
                *(__half2*)(C + (size_t)r0 * LDC + cc) =
                    __float22half2_rn(make_float2(acc[mi][ni][0], acc[mi][ni][1]));
            if (r0 + 8 < M)
                *(__half2*)(C + (size_t)(r0 + 8) * LDC + cc) =
                    __float22half2_rn(make_float2(acc[mi][ni][2], acc[mi][ni][3]));
        }
    }
}

// Static-init: raise dynamic smem limit for k_mma1 (host API, outside capture)
static bool g_attr_ok = [](){
    return cudaFuncSetAttribute(k_mma1<16, 512, 256>,
                                cudaFuncAttributeMaxDynamicSharedMemorySize,
                                G1_SMEM) == cudaSuccess;
}();

// ---------------------------------------------------------------------------
// fp16 mma.sync GEMM (GEMM2): C = A @ B^T, fp16 in, f32 acc, fp16 out
// ---------------------------------------------------------------------------
template<int CCH, int KA, int LDC>
__global__ __launch_bounds__(256) void k_mma(const __half* __restrict__ A,
                                             const __half* __restrict__ B,
                                             __half* __restrict__ C, int M)
{
    constexpr int LDS = 40;
    __shared__ __align__(16) __half As[2][128 * LDS];
    __shared__ __align__(16) __half Bs[2][128 * LDS];

    int tid = threadIdx.x, lane = tid & 31, wid = tid >> 5;
    int m0 = blockIdx.y * 128, n0 = blockIdx.x * 128;
    int wm = (wid >> 2) * 64, wn = (wid & 3) * 32;

    float acc[4][4][4];
    #pragma unroll
    for (int a = 0; a < 4; a++)
        #pragma unroll
        for (int b = 0; b < 4; b++)
            #pragma unroll
            for (int q = 0; q < 4; q++) acc[a][b][q] = 0.f;

    uint32_t aBase = smem_u32(As), bBase = smem_u32(Bs);
    int r_ld = tid >> 1;
    int s0_ld = (tid & 1) * 2;

    auto load = [&](int c, int st) {
        int k0 = c * 32;
        const __half* Ap = A + (size_t)(m0 + r_ld) * KA + k0;
        const __half* Bp = B + (size_t)(n0 + r_ld) * KA + k0;
        int sz = (m0 + r_ld < M) ? 16 : 0;
        uint32_t ad = aBase + (uint32_t)(st * 128 * LDS + r_ld * LDS) * 2;
        uint32_t bd = bBase + (uint32_t)(st * 128 * LDS + r_ld * LDS) * 2;
        #pragma unroll
        for (int i = 0; i < 2; i++) {
            int s = s0_ld + i;
            cp16(ad + s * 16, Ap + s * 8, sz);
            cp16(bd + s * 16, Bp + s * 8, 16);
        }
        cp_commit();
    };

    load(0, 0);
    for (int c = 0; c < CCH; c++) {
        int st = c & 1;
        if (c + 1 < CCH) { load(c + 1, st ^ 1); cp_wait<1>(); }
        else             { cp_wait<0>(); }
        __syncthreads();

        #pragma unroll
        for (int ks = 0; ks < 2; ks++) {
            uint32_t ra[4][4], rb[4][2];
            #pragma unroll
            for (int mi = 0; mi < 4; mi++) {
                int row = wm + mi * 16 + (lane & 15);
                int col = ks * 16 + (lane >> 4) * 8;
                uint32_t ad = aBase + (uint32_t)(st * 128 * LDS + row * LDS + col) * 2;
                asm volatile("ldmatrix.sync.aligned.m8n8.x4.shared.b16 {%0,%1,%2,%3}, [%4];"
                    : "=r"(ra[mi][0]), "=r"(ra[mi][1]), "=r"(ra[mi][2]), "=r"(ra[mi][3])
                    : "r"(ad));
            }
            #pragma unroll
            for (int ni = 0; ni < 4; ni++) {
                int row = wn + ni * 8 + (lane & 7);
                int col = ks * 16 + ((lane >> 3) & 1) * 8;
                uint32_t bd = bBase + (uint32_t)(st * 128 * LDS + row * LDS + col) * 2;
                asm volatile("ldmatrix.sync.aligned.m8n8.x2.shared.b16 {%0,%1}, [%2];"
                    : "=r"(rb[ni][0]), "=r"(rb[ni][1]) : "r"(bd));
            }
            #pragma unroll
            for (int mi = 0; mi < 4; mi++)
                #pragma unroll
                for (int ni = 0; ni < 4; ni++)
                    asm volatile(
                        "mma.sync.aligned.m16n8k16.row.col.f32.f16.f16.f32 "
                        "{%0,%1,%2,%3}, {%4,%5,%6,%7}, {%8,%9}, {%0,%1,%2,%3};"
                        : "+f"(acc[mi][ni][0]), "+f"(acc[mi][ni][1]),
                          "+f"(acc[mi][ni][2]), "+f"(acc[mi][ni][3])
                        : "r"(ra[mi][0]), "r"(ra[mi][1]), "r"(ra[mi][2]), "r"(ra[mi][3]),
                          "r"(rb[ni][0]), "r"(rb[ni][1]));
        }
        __syncthreads();
    }

    #pragma unroll
    for (int mi = 0; mi < 4; mi++) {
        int r0 = m0 + wm + mi * 16 + (lane >> 2);
        #pragma unroll
        for (int ni = 0; ni < 4; ni++) {
            int cc = n0 + wn + ni * 8 + (lane & 3) * 2;
            if (r0 < M)
                *(__half2*)(C + (size_t)r0 * LDC + cc) =
                    __float22half2_rn(make_float2(acc[mi][ni][0], acc[mi][ni][1]));
            if (r0 + 8 < M)
                *(__half2*)(C + (size_t)(r0 + 8) * LDC + cc) =
                    __float22half2_rn(make_float2(acc[mi][ni][2], acc[mi][ni][3]));
        }
    }
}

// ---------------------------------------------------------------------------
// SPMM1: h = relu(A @ xwh + b1), fp16 gather (16B/lane/edge), f32 acc,
// 4x-unrolled MLP, fp16 out; warp/row
// ---------------------------------------------------------------------------
__global__ __launch_bounds__(256) void k_spmm1(const float* __restrict__ b1) {
    int w    = (blockIdx.x * blockDim.x + threadIdx.x) >> 5;
    int lane = threadIdx.x & 31;
    if (w >= NN) return;

    int s0 = g_off[w], s1 = g_off[w + 1];
    float acc[8];
    #pragma unroll
    for (int i = 0; i < 8; i++) acc[i] = 0.f;

    auto fmaV = [&](float we, uint4 v) {
        const __half2* hp = (const __half2*)&v;
        #pragma unroll
        for (int q = 0; q < 4; q++) {
            float2 f = __half22float2(hp[q]);
            acc[2*q]     = fmaf(we, f.x, acc[2*q]);
            acc[2*q + 1] = fmaf(we, f.y, acc[2*q + 1]);
        }
    };

    int e = s0;
    for (; e + 4 <= s1; e += 4) {
        int2 e0 = g_edge[e],     e1 = g_edge[e + 1];
        int2 e2 = g_edge[e + 2], e3 = g_edge[e + 3];
        uint4 v0 = __ldg((const uint4*)(g_xwh + (size_t)e0.x * NH) + lane);
        uint4 v1 = __ldg((const uint4*)(g_xwh + (size_t)e1.x * NH) + lane);
        uint4 v2 = __ldg((const uint4*)(g_xwh + (size_t)e2.x * NH) + lane);
        uint4 v3 = __ldg((const uint4*)(g_xwh + (size_t)e3.x * NH) + lane);
        fmaV(__int_as_float(e0.y), v0);
        fmaV(__int_as_float(e1.y), v1);
        fmaV(__int_as_float(e2.y), v2);
        fmaV(__int_as_float(e3.y), v3);
    }
    for (; e < s1; e++) {
        int2 ed = g_edge[e];
        uint4 v = __ldg((const uint4*)(g_xwh + (size_t)ed.x * NH) + lane);
        fmaV(__int_as_float(ed.y), v);
    }

    const float4* bb = (const float4*)(b1 + lane * 8);
    float4 b0 = __ldg(bb), b1v = __ldg(bb + 1);
    acc[0] = fmaxf(acc[0] + b0.x, 0.f);  acc[1] = fmaxf(acc[1] + b0.y, 0.f);
    acc[2] = fmaxf(acc[2] + b0.z, 0.f);  acc[3] = fmaxf(acc[3] + b0.w, 0.f);
    acc[4] = fmaxf(acc[4] + b1v.x, 0.f); acc[5] = fmaxf(acc[5] + b1v.y, 0.f);
    acc[6] = fmaxf(acc[6] + b1v.z, 0.f); acc[7] = fmaxf(acc[7] + b1v.w, 0.f);

    __half2 hv[4];
    #pragma unroll
    for (int q = 0; q < 4; q++)
        hv[q] = __float22half2_rn(make_float2(acc[2*q], acc[2*q + 1]));
    *(uint4*)(g_h + (size_t)w * NH + lane * 8) = *(uint4*)hv;
}

// ---------------------------------------------------------------------------
// SPMM2: D=128 fp16 gather from g_z (8B/lane/edge), f32 acc, 4x MLP, f32 out
// ---------------------------------------------------------------------------
__global__ __launch_bounds__(256) void k_spmm2(
    const float* __restrict__ bmu, const float* __restrict__ blv,
    float* __restrict__ out)
{
    int w    = (blockIdx.x * blockDim.x + threadIdx.x) >> 5;
    int lane = threadIdx.x & 31;
    if (w >= NN) return;

    int s0 = g_off[w], s1 = g_off[w + 1];
    float acc[4] = {0.f, 0.f, 0.f, 0.f};

    auto fmaV = [&](float we, uint2 v) {
        float2 f0 = __half22float2(*(const __half2*)&v.x);
        float2 f1 = __half22float2(*(const __half2*)&v.y);
        acc[0] = fmaf(we, f0.x, acc[0]);
        acc[1] = fmaf(we, f0.y, acc[1]);
        acc[2] = fmaf(we, f1.x, acc[2]);
        acc[3] = fmaf(we, f1.y, acc[3]);
    };

    int e = s0;
    for (; e + 4 <= s1; e += 4) {
        int2 e0 = g_edge[e],     e1 = g_edge[e + 1];
        int2 e2 = g_edge[e + 2], e3 = g_edge[e + 3];
        uint2 v0 = __ldg((const uint2*)(g_z + (size_t)e0.x * 128) + lane);
        uint2 v1 = __ldg((const uint2*)(g_z + (size_t)e1.x * 128) + lane);
        uint2 v2 = __ldg((const uint2*)(g_z + (size_t)e2.x * 128) + lane);
        uint2 v3 = __ldg((const uint2*)(g_z + (size_t)e3.x * 128) + lane);
        fmaV(__int_as_float(e0.y), v0);
        fmaV(__int_as_float(e1.y), v1);
        fmaV(__int_as_float(e2.y), v2);
        fmaV(__int_as_float(e3.y), v3);
    }
    for (; e < s1; e++) {
        int2 ed = g_edge[e];
        uint2 v = __ldg((const uint2*)(g_z + (size_t)ed.x * 128) + lane);
        fmaV(__int_as_float(ed.y), v);
    }

    int col = lane * 4;
    if (col < 64) {
        float4 b = __ldg((const float4*)(bmu + col));
        *(float4*)(out + (size_t)w * 64 + col) =
            make_float4(acc[0] + b.x, acc[1] + b.y, acc[2] + b.z, acc[3] + b.w);
    } else {
        int jc = col - 64;
        float4 b = __ldg((const float4*)(blv + jc));
        *(float4*)(out + (size_t)NN * 64 + (size_t)w * 64 + jc) =
            make_float4(acc[0] + b.x, acc[1] + b.y, acc[2] + b.z, acc[3] + b.w);
    }
}

// ---------------------------------------------------------------------------
// Launch (serial round-6 schedule; CSR forked; GEMM1 fuses x conversion)
// ---------------------------------------------------------------------------
extern "C" void kernel_launch(void* const* d_in, const int* in_sizes, int n_in,
                              void* d_out, int out_size)
{
    const float* x   = (const float*)d_in[0];
    const int*   ei  = (const int*)  d_in[1];
    const float* ew  = (const float*)d_in[2];
    const float* W1  = (const float*)d_in[3];
    const float* b1  = (const float*)d_in[4];
    const float* Wmu = (const float*)d_in[5];
    const float* bmu = (const float*)d_in[6];
    const float* Wlv = (const float*)d_in[7];
    const float* blv = (const float*)d_in[8];
    float* out = (float*)d_out;

    __half *p_xwh, *p_h, *p_z, *p_B1, *p_B2;
    cudaGetSymbolAddress((void**)&p_xwh, g_xwh);
    cudaGetSymbolAddress((void**)&p_h,   g_h);
    cudaGetSymbolAddress((void**)&p_z,   g_z);
    cudaGetSymbolAddress((void**)&p_B1,  g_B1);
    cudaGetSymbolAddress((void**)&p_B2,  g_B2);

    bool fork = g_ov.ok;
    cudaStream_t sC = fork ? g_ov.s2 : (cudaStream_t)0;

    if (fork) {
        cudaEventRecord(g_ov.eFork, 0);
        cudaStreamWaitEvent(g_ov.s2, g_ov.eFork, 0);
    }

    // CSR by dst (stream sC — overlaps dense chain)
    k_zero_deg<<<(NN + 255) / 256, 256, 0, sC>>>();
    k_hist    <<<(NE + 255) / 256, 256, 0, sC>>>(ei);
    k_scan    <<<1, 1024, 0, sC>>>();
    k_scatter <<<(NE + 255) / 256, 256, 0, sC>>>(ei, ew);
    if (fork) cudaEventRecord(g_ov.eJoin, g_ov.s2);

    // Dense chain (stream 0): weight prep + GEMM1 (in-smem f32->fp16 A conv)
    k_prepB1<<<(256 * 512 + 255) / 256, 256>>>(W1);
    k_prepB2<<<(128 * 256 + 255) / 256, 256>>>(Wmu, Wlv);
    {
        dim3 grid(2, (NN + 127) / 128);
        k_mma1<16, 512, 256><<<grid, 256, G1_SMEM>>>(x, p_B1, p_xwh, NN);
    }

    if (fork) cudaStreamWaitEvent(0, g_ov.eJoin, 0);

    // SPMM1 + bias + relu (single launch)
    k_spmm1<<<(NN + 7) / 8, 256>>>(b1);

    // GEMM2: [mu|logvar] = h @ [Wmu|Wlv]  (K=256), writes g_z
    {
        dim3 grid(1, (NN + 127) / 128);
        k_mma<8, 256, 128><<<grid, 256>>>(p_h, p_B2, p_z, NN);
    }

    // SPMM2 + bias -> d_out (gathers from g_z)
    k_spmm2<<<(NN + 7) / 8, 256>>>(bmu, blv, out);
}

// round 11
// speedup vs baseline: 1.4821x; 1.4821x over previous
#include <cuda_runtime.h>
#include <cuda_fp16.h>
#include <cstdint>

// Problem constants
#define NN 100000      // nodes
#define NE 3200000     // edges
#define NF 512         // in features
#define NH 256         // hidden
#define NL 64          // latent

// ---------------------------------------------------------------------------
// Scratch (device globals -> allocation-free, graph-capturable)
// ---------------------------------------------------------------------------
__device__ __half g_xh [(size_t)NN * NF];   // x in fp16 [NN,512]
__device__ __half g_xwh[(size_t)NN * NH];   // GEMM1 out [NN,256]
__device__ __half g_h  [(size_t)NN * NH];   // relu(spmm1) fp16 [NN,256]
__device__ __half g_z  [(size_t)NN * 128];  // GEMM2 out [NN,128]
__device__ __half g_B1 [(size_t)256 * 512]; // W1^T fp16  [N=256, K=512]
__device__ __half g_B2 [(size_t)128 * 256]; // [Wmu|Wlv]^T fp16 [N=128, K=256]
__device__ int   g_off[NN + 1];
__device__ int   g_deg[NN];
__device__ int   g_cur[NN];
__device__ int2  g_edge[NE];                // .x = src, .y = bits(weight), sorted by dst

// ---------------------------------------------------------------------------
// Streams/events for graph-forked overlap (created at load time)
// ---------------------------------------------------------------------------
struct OverlapRes {
    cudaStream_t s2 = nullptr;
    cudaEvent_t  eFork = nullptr, eJoin = nullptr;
    bool ok = false;
    OverlapRes() {
        ok = (cudaStreamCreateWithFlags(&s2, cudaStreamNonBlocking) == cudaSuccess) &&
             (cudaEventCreateWithFlags(&eFork, cudaEventDisableTiming) == cudaSuccess) &&
             (cudaEventCreateWithFlags(&eJoin, cudaEventDisableTiming) == cudaSuccess);
    }
};
static OverlapRes g_ov;

// ---------------------------------------------------------------------------
// PTX helpers
// ---------------------------------------------------------------------------
__device__ __forceinline__ uint32_t smem_u32(const void* p) {
    uint32_t a;
    asm("{ .reg .u64 t; cvta.to.shared.u64 t, %1; cvt.u32.u64 %0, t; }" : "=r"(a) : "l"(p));
    return a;
}
__device__ __forceinline__ void cp16(uint32_t dst, const void* src, int sz) {
    asm volatile("cp.async.cg.shared.global [%0], [%1], 16, %2;"
                 :: "r"(dst), "l"(src), "r"(sz) : "memory");
}
__device__ __forceinline__ void cp_commit() {
    asm volatile("cp.async.commit_group;" ::: "memory");
}
template<int N> __device__ __forceinline__ void cp_wait() {
    asm volatile("cp.async.wait_group %0;" :: "n"(N) : "memory");
}

// ---------------------------------------------------------------------------
// CSR build
// ---------------------------------------------------------------------------
__global__ void k_zero_deg() {
    int i = blockIdx.x * blockDim.x + threadIdx.x;
    if (i < NN) g_deg[i] = 0;
}
__global__ void k_hist(const int* __restrict__ ei) {
    int e = blockIdx.x * blockDim.x + threadIdx.x;
    if (e < NE) atomicAdd(&g_deg[__ldg(ei + NE + e)], 1);
}
__global__ void k_scan() {
    __shared__ int wsum[32];
    int tid = threadIdx.x, lane = tid & 31, wid = tid >> 5;
    int carry = 0;
    for (int base = 0; base < NN; base += 1024) {
        int i = base + tid;
        int v = (i < NN) ? g_deg[i] : 0;
        int x = v;
        #pragma unroll
        for (int o = 1; o < 32; o <<= 1) {
            int y = __shfl_up_sync(0xffffffffu, x, o);
            if (lane >= o) x += y;
        }
        if (lane == 31) wsum[wid] = x;
        __syncthreads();
        if (wid == 0) {
            int s = wsum[lane];
            #pragma unroll
            for (int o = 1; o < 32; o <<= 1) {
                int y = __shfl_up_sync(0xffffffffu, s, o);
                if (lane >= o) s += y;
            }
            wsum[lane] = s;
        }
        __syncthreads();
        int excl = carry + x - v + (wid ? wsum[wid - 1] : 0);
        if (i < NN) { g_off[i] = excl; g_cur[i] = excl; }
        carry += wsum[31];
        __syncthreads();
    }
    if (tid == 0) g_off[NN] = carry;
}
__global__ void k_scatter(const int* __restrict__ ei, const float* __restrict__ ew) {
    int e = blockIdx.x * blockDim.x + threadIdx.x;
    if (e < NE) {
        int src = __ldg(ei + e);
        int dst = __ldg(ei + NE + e);
        float w = __ldg(ew + e);
        int pos = atomicAdd(&g_cur[dst], 1);
        g_edge[pos] = make_int2(src, __float_as_int(w));
    }
}

// ---------------------------------------------------------------------------
// fp16 prep
// ---------------------------------------------------------------------------
__global__ __launch_bounds__(256) void k_conv_x(const float* __restrict__ x) {
    int t = blockIdx.x * blockDim.x + threadIdx.x;   // one float4 -> half4
    if (t >= NN * 128) return;
    float4 v = ((const float4*)x)[t];
    __half2 h0 = __float22half2_rn(make_float2(v.x, v.y));
    __half2 h1 = __float22half2_rn(make_float2(v.z, v.w));
    ((__half2*)g_xh)[t * 2]     = h0;
    ((__half2*)g_xh)[t * 2 + 1] = h1;
}
__global__ __launch_bounds__(256) void k_prepB1(const float* __restrict__ W1) {
    int t = blockIdx.x * blockDim.x + threadIdx.x;
    if (t >= 256 * 512) return;
    int n = t >> 9, k = t & 511;
    g_B1[t] = __float2half_rn(W1[(size_t)k * 256 + n]);
}
__global__ __launch_bounds__(256) void k_prepB2(const float* __restrict__ Wmu,
                                                const float* __restrict__ Wlv) {
    int t = blockIdx.x * blockDim.x + threadIdx.x;
    if (t >= 128 * 256) return;
    int n = t >> 8, k = t & 255;
    float w = (n < 64) ? Wmu[(size_t)k * 64 + n] : Wlv[(size_t)k * 64 + (n - 64)];
    g_B2[t] = __float2half_rn(w);
}

// ---------------------------------------------------------------------------
// fp16 mma.sync GEMM: C[128x128 tile] = A @ B^T, fp16 in, f32 acc, fp16 out
//   A: [M, KA] row-major fp16; B: [N, KA] K-contig fp16; CCH chunks of K=32
// ---------------------------------------------------------------------------
template<int CCH, int KA, int LDC>
__global__ __launch_bounds__(256) void k_mma(const __half* __restrict__ A,
                                             const __half* __restrict__ B,
                                             __half* __restrict__ C, int M)
{
    constexpr int LDS = 40;
    __shared__ __align__(16) __half As[2][128 * LDS];
    __shared__ __align__(16) __half Bs[2][128 * LDS];

    int tid = threadIdx.x, lane = tid & 31, wid = tid >> 5;
    int m0 = blockIdx.y * 128, n0 = blockIdx.x * 128;
    int wm = (wid >> 2) * 64, wn = (wid & 3) * 32;

    float acc[4][4][4];
    #pragma unroll
    for (int a = 0; a < 4; a++)
        #pragma unroll
        for (int b = 0; b < 4; b++)
            #pragma unroll
            for (int q = 0; q < 4; q++) acc[a][b][q] = 0.f;

    uint32_t aBase = smem_u32(As), bBase = smem_u32(Bs);
    int r_ld = tid >> 1;
    int s0_ld = (tid & 1) * 2;

    auto load = [&](int c, int st) {
        int k0 = c * 32;
        const __half* Ap = A + (size_t)(m0 + r_ld) * KA + k0;
        const __half* Bp = B + (size_t)(n0 + r_ld) * KA + k0;
        int sz = (m0 + r_ld < M) ? 16 : 0;
        uint32_t ad = aBase + (uint32_t)(st * 128 * LDS + r_ld * LDS) * 2;
        uint32_t bd = bBase + (uint32_t)(st * 128 * LDS + r_ld * LDS) * 2;
        #pragma unroll
        for (int i = 0; i < 2; i++) {
            int s = s0_ld + i;
            cp16(ad + s * 16, Ap + s * 8, sz);
            cp16(bd + s * 16, Bp + s * 8, 16);
        }
        cp_commit();
    };

    load(0, 0);
    for (int c = 0; c < CCH; c++) {
        int st = c & 1;
        if (c + 1 < CCH) { load(c + 1, st ^ 1); cp_wait<1>(); }
        else             { cp_wait<0>(); }
        __syncthreads();

        #pragma unroll
        for (int ks = 0; ks < 2; ks++) {
            uint32_t ra[4][4], rb[4][2];
            #pragma unroll
            for (int mi = 0; mi < 4; mi++) {
                int row = wm + mi * 16 + (lane & 15);
                int col = ks * 16 + (lane >> 4) * 8;
                uint32_t ad = aBase + (uint32_t)(st * 128 * LDS + row * LDS + col) * 2;
                asm volatile("ldmatrix.sync.aligned.m8n8.x4.shared.b16 {%0,%1,%2,%3}, [%4];"
                    : "=r"(ra[mi][0]), "=r"(ra[mi][1]), "=r"(ra[mi][2]), "=r"(ra[mi][3])
                    : "r"(ad));
            }
            #pragma unroll
            for (int ni = 0; ni < 4; ni++) {
                int row = wn + ni * 8 + (lane & 7);
                int col = ks * 16 + ((lane >> 3) & 1) * 8;
                uint32_t bd = bBase + (uint32_t)(st * 128 * LDS + row * LDS + col) * 2;
                asm volatile("ldmatrix.sync.aligned.m8n8.x2.shared.b16 {%0,%1}, [%2];"
                    : "=r"(rb[ni][0]), "=r"(rb[ni][1]) : "r"(bd));
            }
            #pragma unroll
            for (int mi = 0; mi < 4; mi++)
                #pragma unroll
                for (int ni = 0; ni < 4; ni++)
                    asm volatile(
                        "mma.sync.aligned.m16n8k16.row.col.f32.f16.f16.f32 "
                        "{%0,%1,%2,%3}, {%4,%5,%6,%7}, {%8,%9}, {%0,%1,%2,%3};"
                        : "+f"(acc[mi][ni][0]), "+f"(acc[mi][ni][1]),
                          "+f"(acc[mi][ni][2]), "+f"(acc[mi][ni][3])
                        : "r"(ra[mi][0]), "r"(ra[mi][1]), "r"(ra[mi][2]), "r"(ra[mi][3]),
                          "r"(rb[ni][0]), "r"(rb[ni][1]));
        }
        __syncthreads();
    }

    #pragma unroll
    for (int mi = 0; mi < 4; mi++) {
        int r0 = m0 + wm + mi * 16 + (lane >> 2);
        #pragma unroll
        for (int ni = 0; ni < 4; ni++) {
            int cc = n0 + wn + ni * 8 + (lane & 3) * 2;
            if (r0 < M)
                *(__half2*)(C + (size_t)r0 * LDC + cc) =
                    __float22half2_rn(make_float2(acc[mi][ni][0], acc[mi][ni][1]));
            if (r0 + 8 < M)
                *(__half2*)(C + (size_t)(r0 + 8) * LDC + cc) =
                    __float22half2_rn(make_float2(acc[mi][ni][2], acc[mi][ni][3]));
        }
    }
}

// ---------------------------------------------------------------------------
// SPMM1: h = relu(A @ xwh + b1), fp16 gather (16B/lane/edge), f32 acc,
// 4x-unrolled MLP, fp16 out; warp/row
// ---------------------------------------------------------------------------
__global__ __launch_bounds__(256) void k_spmm1(const float* __restrict__ b1) {
    int w    = (blockIdx.x * blockDim.x + threadIdx.x) >> 5;
    int lane = threadIdx.x & 31;
    if (w >= NN) return;

    int s0 = g_off[w], s1 = g_off[w + 1];
    float acc[8];
    #pragma unroll
    for (int i = 0; i < 8; i++) acc[i] = 0.f;

    auto fmaV = [&](float we, uint4 v) {
        const __half2* hp = (const __half2*)&v;
        #pragma unroll
        for (int q = 0; q < 4; q++) {
            float2 f = __half22float2(hp[q]);
            acc[2*q]     = fmaf(we, f.x, acc[2*q]);
            acc[2*q + 1] = fmaf(we, f.y, acc[2*q + 1]);
        }
    };

    int e = s0;
    for (; e + 4 <= s1; e += 4) {
        int2 e0 = g_edge[e],     e1 = g_edge[e + 1];
        int2 e2 = g_edge[e + 2], e3 = g_edge[e + 3];
        uint4 v0 = __ldg((const uint4*)(g_xwh + (size_t)e0.x * NH) + lane);
        uint4 v1 = __ldg((const uint4*)(g_xwh + (size_t)e1.x * NH) + lane);
        uint4 v2 = __ldg((const uint4*)(g_xwh + (size_t)e2.x * NH) + lane);
        uint4 v3 = __ldg((const uint4*)(g_xwh + (size_t)e3.x * NH) + lane);
        fmaV(__int_as_float(e0.y), v0);
        fmaV(__int_as_float(e1.y), v1);
        fmaV(__int_as_float(e2.y), v2);
        fmaV(__int_as_float(e3.y), v3);
    }
    for (; e < s1; e++) {
        int2 ed = g_edge[e];
        uint4 v = __ldg((const uint4*)(g_xwh + (size_t)ed.x * NH) + lane);
        fmaV(__int_as_float(ed.y), v);
    }

    const float4* bb = (const float4*)(b1 + lane * 8);
    float4 b0 = __ldg(bb), b1v = __ldg(bb + 1);
    acc[0] = fmaxf(acc[0] + b0.x, 0.f);  acc[1] = fmaxf(acc[1] + b0.y, 0.f);
    acc[2] = fmaxf(acc[2] + b0.z, 0.f);  acc[3] = fmaxf(acc[3] + b0.w, 0.f);
    acc[4] = fmaxf(acc[4] + b1v.x, 0.f); acc[5] = fmaxf(acc[5] + b1v.y, 0.f);
    acc[6] = fmaxf(acc[6] + b1v.z, 0.f); acc[7] = fmaxf(acc[7] + b1v.w, 0.f);

    __half2 hv[4];
    #pragma unroll
    for (int q = 0; q < 4; q++)
        hv[q] = __float22half2_rn(make_float2(acc[2*q], acc[2*q + 1]));
    *(uint4*)(g_h + (size_t)w * NH + lane * 8) = *(uint4*)hv;
}

// ---------------------------------------------------------------------------
// SPMM2: D=128 fp16 gather from g_z (8B/lane/edge), f32 acc, 4x MLP, f32 out
// ---------------------------------------------------------------------------
__global__ __launch_bounds__(256) void k_spmm2(
    const float* __restrict__ bmu, const float* __restrict__ blv,
    float* __restrict__ out)
{
    int w    = (blockIdx.x * blockDim.x + threadIdx.x) >> 5;
    int lane = threadIdx.x & 31;
    if (w >= NN) return;

    int s0 = g_off[w], s1 = g_off[w + 1];
    float acc[4] = {0.f, 0.f, 0.f, 0.f};

    auto fmaV = [&](float we, uint2 v) {
        float2 f0 = __half22float2(*(const __half2*)&v.x);
        float2 f1 = __half22float2(*(const __half2*)&v.y);
        acc[0] = fmaf(we, f0.x, acc[0]);
        acc[1] = fmaf(we, f0.y, acc[1]);
        acc[2] = fmaf(we, f1.x, acc[2]);
        acc[3] = fmaf(we, f1.y, acc[3]);
    };

    int e = s0;
    for (; e + 4 <= s1; e += 4) {
        int2 e0 = g_edge[e],     e1 = g_edge[e + 1];
        int2 e2 = g_edge[e + 2], e3 = g_edge[e + 3];
        uint2 v0 = __ldg((const uint2*)(g_z + (size_t)e0.x * 128) + lane);
        uint2 v1 = __ldg((const uint2*)(g_z + (size_t)e1.x * 128) + lane);
        uint2 v2 = __ldg((const uint2*)(g_z + (size_t)e2.x * 128) + lane);
        uint2 v3 = __ldg((const uint2*)(g_z + (size_t)e3.x * 128) + lane);
        fmaV(__int_as_float(e0.y), v0);
        fmaV(__int_as_float(e1.y), v1);
        fmaV(__int_as_float(e2.y), v2);
        fmaV(__int_as_float(e3.y), v3);
    }
    for (; e < s1; e++) {
        int2 ed = g_edge[e];
        uint2 v = __ldg((const uint2*)(g_z + (size_t)ed.x * 128) + lane);
        fmaV(__int_as_float(ed.y), v);
    }

    int col = lane * 4;
    if (col < 64) {
        float4 b = __ldg((const float4*)(bmu + col));
        *(float4*)(out + (size_t)w * 64 + col) =
            make_float4(acc[0] + b.x, acc[1] + b.y, acc[2] + b.z, acc[3] + b.w);
    } else {
        int jc = col - 64;
        float4 b = __ldg((const float4*)(blv + jc));
        *(float4*)(out + (size_t)NN * 64 + (size_t)w * 64 + jc) =
            make_float4(acc[0] + b.x, acc[1] + b.y, acc[2] + b.z, acc[3] + b.w);
    }
}

// ---------------------------------------------------------------------------
// Launch (round-6 serial schedule; CSR forked on s2)
// ---------------------------------------------------------------------------
extern "C" void kernel_launch(void* const* d_in, const int* in_sizes, int n_in,
                              void* d_out, int out_size)
{
    const float* x   = (const float*)d_in[0];
    const int*   ei  = (const int*)  d_in[1];
    const float* ew  = (const float*)d_in[2];
    const float* W1  = (const float*)d_in[3];
    const float* b1  = (const float*)d_in[4];
    const float* Wmu = (const float*)d_in[5];
    const float* bmu = (const float*)d_in[6];
    const float* Wlv = (const float*)d_in[7];
    const float* blv = (const float*)d_in[8];
    float* out = (float*)d_out;

    __half *p_xh, *p_xwh, *p_h, *p_z, *p_B1, *p_B2;
    cudaGetSymbolAddress((void**)&p_xh,  g_xh);
    cudaGetSymbolAddress((void**)&p_xwh, g_xwh);
    cudaGetSymbolAddress((void**)&p_h,   g_h);
    cudaGetSymbolAddress((void**)&p_z,   g_z);
    cudaGetSymbolAddress((void**)&p_B1,  g_B1);
    cudaGetSymbolAddress((void**)&p_B2,  g_B2);

    bool fork = g_ov.ok;
    cudaStream_t sC = fork ? g_ov.s2 : (cudaStream_t)0;

    if (fork) {
        cudaEventRecord(g_ov.eFork, 0);
        cudaStreamWaitEvent(g_ov.s2, g_ov.eFork, 0);
    }

    // CSR by dst (stream sC — overlaps dense chain)
    k_zero_deg<<<(NN + 255) / 256, 256, 0, sC>>>();
    k_hist    <<<(NE + 255) / 256, 256, 0, sC>>>(ei);
    k_scan    <<<1, 1024, 0, sC>>>();
    k_scatter <<<(NE + 255) / 256, 256, 0, sC>>>(ei, ew);
    if (fork) cudaEventRecord(g_ov.eJoin, g_ov.s2);

    // Dense chain (stream 0): prep + conv + GEMM1 (pure fp16, cp.async)
    k_prepB1<<<(256 * 512 + 255) / 256, 256>>>(W1);
    k_prepB2<<<(128 * 256 + 255) / 256, 256>>>(Wmu, Wlv);
    k_conv_x<<<(NN * 128 + 255) / 256, 256>>>(x);
    {
        dim3 grid(2, (NN + 127) / 128);
        k_mma<16, 512, 256><<<grid, 256>>>(p_xh, p_B1, p_xwh, NN);
    }

    if (fork) cudaStreamWaitEvent(0, g_ov.eJoin, 0);

    // SPMM1 + bias + relu (single launch)
    k_spmm1<<<(NN + 7) / 8, 256>>>(b1);

    // GEMM2: [mu|logvar] = h @ [Wmu|Wlv]  (K=256), writes g_z
    {
        dim3 grid(1, (NN + 127) / 128);
        k_mma<8, 256, 128><<<grid, 256>>>(p_h, p_B2, p_z, NN);
    }

    // SPMM2 + bias -> d_out (gathers from g_z)
    k_spmm2<<<(NN + 7) / 8, 256>>>(bmu, blv, out);
}

// round 12
// speedup vs baseline: 1.4855x; 1.0022x over previous
#include <cuda_runtime.h>
#include <cuda_fp16.h>
#include <cstdint>

// Problem constants
#define NN 100000      // nodes
#define NE 3200000     // edges
#define NF 512         // in features
#define NH 256         // hidden
#define NL 64          // latent

#define ROWSPLIT 50048 // = 391 * 128 (conv_x / GEMM1 pipeline split)

// ---------------------------------------------------------------------------
// Scratch (device globals -> allocation-free, graph-capturable)
// ---------------------------------------------------------------------------
__device__ __half g_xh [(size_t)NN * NF];   // x in fp16 [NN,512]
__device__ __half g_xwh[(size_t)NN * NH];   // GEMM1 out [NN,256]; reused as GEMM2 out [NN,128]
__device__ __half g_h  [(size_t)NN * NH];   // relu(spmm1) fp16 [NN,256]
__device__ __half g_B1 [(size_t)256 * 512]; // W1^T fp16  [N=256, K=512]
__device__ __half g_B2 [(size_t)128 * 256]; // [Wmu|Wlv]^T fp16 [N=128, K=256]
__device__ int   g_off[NN + 1];
__device__ int   g_deg[NN];
__device__ int   g_cur[NN];
__device__ int2  g_edge[NE];                // .x = src, .y = bits(weight), sorted by dst

// ---------------------------------------------------------------------------
// Streams/events for graph-forked overlap (created at load time)
// ---------------------------------------------------------------------------
struct OverlapRes {
    cudaStream_t s2 = nullptr, s3 = nullptr;
    cudaEvent_t  eFork = nullptr, eJoin = nullptr;
    cudaEvent_t  eC0 = nullptr, eC1 = nullptr, eG1 = nullptr;
    bool ok = false;
    OverlapRes() {
        ok = (cudaStreamCreateWithFlags(&s2, cudaStreamNonBlocking) == cudaSuccess) &&
             (cudaStreamCreateWithFlags(&s3, cudaStreamNonBlocking) == cudaSuccess) &&
             (cudaEventCreateWithFlags(&eFork, cudaEventDisableTiming) == cudaSuccess) &&
             (cudaEventCreateWithFlags(&eJoin, cudaEventDisableTiming) == cudaSuccess) &&
             (cudaEventCreateWithFlags(&eC0,   cudaEventDisableTiming) == cudaSuccess) &&
             (cudaEventCreateWithFlags(&eC1,   cudaEventDisableTiming) == cudaSuccess) &&
             (cudaEventCreateWithFlags(&eG1,   cudaEventDisableTiming) == cudaSuccess);
    }
};
static OverlapRes g_ov;

// ---------------------------------------------------------------------------
// PTX helpers
// ---------------------------------------------------------------------------
__device__ __forceinline__ uint32_t smem_u32(const void* p) {
    uint32_t a;
    asm("{ .reg .u64 t; cvta.to.shared.u64 t, %1; cvt.u32.u64 %0, t; }" : "=r"(a) : "l"(p));
    return a;
}
__device__ __forceinline__ void cp16(uint32_t dst, const void* src, int sz) {
    asm volatile("cp.async.cg.shared.global [%0], [%1], 16, %2;"
                 :: "r"(dst), "l"(src), "r"(sz) : "memory");
}
__device__ __forceinline__ void cp_commit() {
    asm volatile("cp.async.commit_group;" ::: "memory");
}
template<int N> __device__ __forceinline__ void cp_wait() {
    asm volatile("cp.async.wait_group %0;" :: "n"(N) : "memory");
}

// ---------------------------------------------------------------------------
// CSR build
// ---------------------------------------------------------------------------
__global__ void k_zero_deg() {
    int i = blockIdx.x * blockDim.x + threadIdx.x;
    if (i < NN) g_deg[i] = 0;
}
__global__ void k_hist(const int* __restrict__ ei) {
    int e = blockIdx.x * blockDim.x + threadIdx.x;
    if (e < NE) atomicAdd(&g_deg[__ldg(ei + NE + e)], 1);
}
__global__ void k_scan() {
    __shared__ int wsum[32];
    int tid = threadIdx.x, lane = tid & 31, wid = tid >> 5;
    int carry = 0;
    for (int base = 0; base < NN; base += 1024) {
        int i = base + tid;
        int v = (i < NN) ? g_deg[i] : 0;
        int x = v;
        #pragma unroll
        for (int o = 1; o < 32; o <<= 1) {
            int y = __shfl_up_sync(0xffffffffu, x, o);
            if (lane >= o) x += y;
        }
        if (lane == 31) wsum[wid] = x;
        __syncthreads();
        if (wid == 0) {
            int s = wsum[lane];
            #pragma unroll
            for (int o = 1; o < 32; o <<= 1) {
                int y = __shfl_up_sync(0xffffffffu, s, o);
                if (lane >= o) s += y;
            }
            wsum[lane] = s;
        }
        __syncthreads();
        int excl = carry + x - v + (wid ? wsum[wid - 1] : 0);
        if (i < NN) { g_off[i] = excl; g_cur[i] = excl; }
        carry += wsum[31];
        __syncthreads();
    }
    if (tid == 0) g_off[NN] = carry;
}
__global__ void k_scatter(const int* __restrict__ ei, const float* __restrict__ ew) {
    int e = blockIdx.x * blockDim.x + threadIdx.x;
    if (e < NE) {
        int src = __ldg(ei + e);
        int dst = __ldg(ei + NE + e);
        float w = __ldg(ew + e);
        int pos = atomicAdd(&g_cur[dst], 1);
        g_edge[pos] = make_int2(src, __float_as_int(w));
    }
}

// ---------------------------------------------------------------------------
// fp16 prep
// ---------------------------------------------------------------------------
// x f32 -> g_xh fp16 over float4 index range [t0, t0+tc)
__global__ __launch_bounds__(256) void k_conv_x(const float* __restrict__ x,
                                                int t0, int tc) {
    int t = blockIdx.x * blockDim.x + threadIdx.x;
    if (t >= tc) return;
    int tt = t0 + t;
    float4 v = ((const float4*)x)[tt];
    __half2 h0 = __float22half2_rn(make_float2(v.x, v.y));
    __half2 h1 = __float22half2_rn(make_float2(v.z, v.w));
    ((__half2*)g_xh)[tt * 2]     = h0;
    ((__half2*)g_xh)[tt * 2 + 1] = h1;
}
__global__ __launch_bounds__(256) void k_prepB1(const float* __restrict__ W1) {
    int t = blockIdx.x * blockDim.x + threadIdx.x;
    if (t >= 256 * 512) return;
    int n = t >> 9, k = t & 511;
    g_B1[t] = __float2half_rn(W1[(size_t)k * 256 + n]);
}
__global__ __launch_bounds__(256) void k_prepB2(const float* __restrict__ Wmu,
                                                const float* __restrict__ Wlv) {
    int t = blockIdx.x * blockDim.x + threadIdx.x;
    if (t >= 128 * 256) return;
    int n = t >> 8, k = t & 255;
    float w = (n < 64) ? Wmu[(size_t)k * 64 + n] : Wlv[(size_t)k * 64 + (n - 64)];
    g_B2[t] = __float2half_rn(w);
}

// ---------------------------------------------------------------------------
// fp16 mma.sync GEMM: C[128x128 tile] = A @ B^T, fp16 in, f32 acc, fp16 out
//   A: [M, KA] row-major fp16; B: [N, KA] K-contig fp16; CCH chunks of K=32
//   moff: M-tile offset for pipelined half launches
// ---------------------------------------------------------------------------
template<int CCH, int KA, int LDC>
__global__ __launch_bounds__(256) void k_mma(const __half* __restrict__ A,
                                             const __half* __restrict__ B,
                                             __half* __restrict__ C, int M, int moff)
{
    constexpr int LDS = 40;
    __shared__ __align__(16) __half As[2][128 * LDS];
    __shared__ __align__(16) __half Bs[2][128 * LDS];

    int tid = threadIdx.x, lane = tid & 31, wid = tid >> 5;
    int m0 = (blockIdx.y + moff) * 128, n0 = blockIdx.x * 128;
    int wm = (wid >> 2) * 64, wn = (wid & 3) * 32;

    float acc[4][4][4];
    #pragma unroll
    for (int a = 0; a < 4; a++)
        #pragma unroll
        for (int b = 0; b < 4; b++)
            #pragma unroll
            for (int q = 0; q < 4; q++) acc[a][b][q] = 0.f;

    uint32_t aBase = smem_u32(As), bBase = smem_u32(Bs);
    int r_ld = tid >> 1;
    int s0_ld = (tid & 1) * 2;

    auto load = [&](int c, int st) {
        int k0 = c * 32;
        const __half* Ap = A + (size_t)(m0 + r_ld) * KA + k0;
        const __half* Bp = B + (size_t)(n0 + r_ld) * KA + k0;
        int sz = (m0 + r_ld < M) ? 16 : 0;
        uint32_t ad = aBase + (uint32_t)(st * 128 * LDS + r_ld * LDS) * 2;
        uint32_t bd = bBase + (uint32_t)(st * 128 * LDS + r_ld * LDS) * 2;
        #pragma unroll
        for (int i = 0; i < 2; i++) {
            int s = s0_ld + i;
            cp16(ad + s * 16, Ap + s * 8, sz);
            cp16(bd + s * 16, Bp + s * 8, 16);
        }
        cp_commit();
    };

    load(0, 0);
    for (int c = 0; c < CCH; c++) {
        int st = c & 1;
        if (c + 1 < CCH) { load(c + 1, st ^ 1); cp_wait<1>(); }
        else             { cp_wait<0>(); }
        __syncthreads();

        #pragma unroll
        for (int ks = 0; ks < 2; ks++) {
            uint32_t ra[4][4], rb[4][2];
            #pragma unroll
            for (int mi = 0; mi < 4; mi++) {
                int row = wm + mi * 16 + (lane & 15);
                int col = ks * 16 + (lane >> 4) * 8;
                uint32_t ad = aBase + (uint32_t)(st * 128 * LDS + row * LDS + col) * 2;
                asm volatile("ldmatrix.sync.aligned.m8n8.x4.shared.b16 {%0,%1,%2,%3}, [%4];"
                    : "=r"(ra[mi][0]), "=r"(ra[mi][1]), "=r"(ra[mi][2]), "=r"(ra[mi][3])
                    : "r"(ad));
            }
            #pragma unroll
            for (int ni = 0; ni < 4; ni++) {
                int row = wn + ni * 8 + (lane & 7);
                int col = ks * 16 + ((lane >> 3) & 1) * 8;
                uint32_t bd = bBase + (uint32_t)(st * 128 * LDS + row * LDS + col) * 2;
                asm volatile("ldmatrix.sync.aligned.m8n8.x2.shared.b16 {%0,%1}, [%2];"
                    : "=r"(rb[ni][0]), "=r"(rb[ni][1]) : "r"(bd));
            }
            #pragma unroll
            for (int mi = 0; mi < 4; mi++)
                #pragma unroll
                for (int ni = 0; ni < 4; ni++)
                    asm volatile(
                        "mma.sync.aligned.m16n8k16.row.col.f32.f16.f16.f32 "
                        "{%0,%1,%2,%3}, {%4,%5,%6,%7}, {%8,%9}, {%0,%1,%2,%3};"
                        : "+f"(acc[mi][ni][0]), "+f"(acc[mi][ni][1]),
                          "+f"(acc[mi][ni][2]), "+f"(acc[mi][ni][3])
                        : "r"(ra[mi][0]), "r"(ra[mi][1]), "r"(ra[mi][2]), "r"(ra[mi][3]),
                          "r"(rb[ni][0]), "r"(rb[ni][1]));
        }
        __syncthreads();
    }

    #pragma unroll
    for (int mi = 0; mi < 4; mi++) {
        int r0 = m0 + wm + mi * 16 + (lane >> 2);
        #pragma unroll
        for (int ni = 0; ni < 4; ni++) {
            int cc = n0 + wn + ni * 8 + (lane & 3) * 2;
            if (r0 < M)
                *(__half2*)(C + (size_t)r0 * LDC + cc) =
                    __float22half2_rn(make_float2(acc[mi][ni][0], acc[mi][ni][1]));
            if (r0 + 8 < M)
                *(__half2*)(C + (size_t)(r0 + 8) * LDC + cc) =
                    __float22half2_rn(make_float2(acc[mi][ni][2], acc[mi][ni][3]));
        }
    }
}

// ---------------------------------------------------------------------------
// SPMM1: h = relu(A @ xwh + b1), fp16 gather (16B/lane/edge), f32 acc,
// 2x-unrolled (round-6 proven form), fp16 out; warp/row
// ---------------------------------------------------------------------------
__global__ __launch_bounds__(256) void k_spmm1(const float* __restrict__ b1) {
    int w    = (blockIdx.x * blockDim.x + threadIdx.x) >> 5;
    int lane = threadIdx.x & 31;
    if (w >= NN) return;

    int s0 = g_off[w], s1 = g_off[w + 1];
    float acc[8];
    #pragma unroll
    for (int i = 0; i < 8; i++) acc[i] = 0.f;

    auto addEdge = [&](int2 ed) {
        float we = __int_as_float(ed.y);
        uint4 v = __ldg((const uint4*)(g_xwh + (size_t)ed.x * NH) + lane);
        const __half2* hp = (const __half2*)&v;
        #pragma unroll
        for (int q = 0; q < 4; q++) {
            float2 f = __half22float2(hp[q]);
            acc[2*q]     = fmaf(we, f.x, acc[2*q]);
            acc[2*q + 1] = fmaf(we, f.y, acc[2*q + 1]);
        }
    };

    int e = s0;
    for (; e + 2 <= s1; e += 2) { addEdge(g_edge[e]); addEdge(g_edge[e + 1]); }
    if (e < s1) addEdge(g_edge[e]);

    const float4* bb = (const float4*)(b1 + lane * 8);
    float4 b0 = __ldg(bb), b1v = __ldg(bb + 1);
    acc[0] = fmaxf(acc[0] + b0.x, 0.f);  acc[1] = fmaxf(acc[1] + b0.y, 0.f);
    acc[2] = fmaxf(acc[2] + b0.z, 0.f);  acc[3] = fmaxf(acc[3] + b0.w, 0.f);
    acc[4] = fmaxf(acc[4] + b1v.x, 0.f); acc[5] = fmaxf(acc[5] + b1v.y, 0.f);
    acc[6] = fmaxf(acc[6] + b1v.z, 0.f); acc[7] = fmaxf(acc[7] + b1v.w, 0.f);

    __half2 hv[4];
    #pragma unroll
    for (int q = 0; q < 4; q++)
        hv[q] = __float22half2_rn(make_float2(acc[2*q], acc[2*q + 1]));
    *(uint4*)(g_h + (size_t)w * NH + lane * 8) = *(uint4*)hv;
}

// ---------------------------------------------------------------------------
// SPMM2: D=128 fp16 gather from g_xwh (8B/lane/edge), f32 acc, 2x unroll,
// bias, final f32 out. (Round-6 proven form; g_xwh reused as GEMM2 out.)
// ---------------------------------------------------------------------------
__global__ __launch_bounds__(256) void k_spmm2(
    const float* __restrict__ bmu, const float* __restrict__ blv,
    float* __restrict__ out)
{
    int w    = (blockIdx.x * blockDim.x + threadIdx.x) >> 5;
    int lane = threadIdx.x & 31;
    if (w >= NN) return;

    int s0 = g_off[w], s1 = g_off[w + 1];
    float acc[4] = {0.f, 0.f, 0.f, 0.f};

    auto addEdge = [&](int2 ed) {
        float we = __int_as_float(ed.y);
        uint2 v = __ldg((const uint2*)(g_xwh + (size_t)ed.x * 128) + lane);
        float2 f0 = __half22float2(*(const __half2*)&v.x);
        float2 f1 = __half22float2(*(const __half2*)&v.y);
        acc[0] = fmaf(we, f0.x, acc[0]);
        acc[1] = fmaf(we, f0.y, acc[1]);
        acc[2] = fmaf(we, f1.x, acc[2]);
        acc[3] = fmaf(we, f1.y, acc[3]);
    };

    int e = s0;
    for (; e + 2 <= s1; e += 2) { addEdge(g_edge[e]); addEdge(g_edge[e + 1]); }
    if (e < s1) addEdge(g_edge[e]);

    int col = lane * 4;
    if (col < 64) {
        float4 b = __ldg((const float4*)(bmu + col));
        *(float4*)(out + (size_t)w * 64 + col) =
            make_float4(acc[0] + b.x, acc[1] + b.y, acc[2] + b.z, acc[3] + b.w);
    } else {
        int jc = col - 64;
        float4 b = __ldg((const float4*)(blv + jc));
        *(float4*)(out + (size_t)NN * 64 + (size_t)w * 64 + jc) =
            make_float4(acc[0] + b.x, acc[1] + b.y, acc[2] + b.z, acc[3] + b.w);
    }
}

// ---------------------------------------------------------------------------
// Launch
// ---------------------------------------------------------------------------
extern "C" void kernel_launch(void* const* d_in, const int* in_sizes, int n_in,
                              void* d_out, int out_size)
{
    const float* x   = (const float*)d_in[0];
    const int*   ei  = (const int*)  d_in[1];
    const float* ew  = (const float*)d_in[2];
    const float* W1  = (const float*)d_in[3];
    const float* b1  = (const float*)d_in[4];
    const float* Wmu = (const float*)d_in[5];
    const float* bmu = (const float*)d_in[6];
    const float* Wlv = (const float*)d_in[7];
    const float* blv = (const float*)d_in[8];
    float* out = (float*)d_out;

    __half *p_xh, *p_xwh, *p_h, *p_B1, *p_B2;
    cudaGetSymbolAddress((void**)&p_xh,  g_xh);
    cudaGetSymbolAddress((void**)&p_xwh, g_xwh);
    cudaGetSymbolAddress((void**)&p_h,   g_h);
    cudaGetSymbolAddress((void**)&p_B1,  g_B1);
    cudaGetSymbolAddress((void**)&p_B2,  g_B2);

    bool fork = g_ov.ok;

    const int TC0 = ROWSPLIT * 128;            // float4s in half0
    const int TC1 = NN * 128 - TC0;            // float4s in half1
    const int T0  = ROWSPLIT / 128;            // 391 M-tiles
    const int T1  = (NN + 127) / 128 - T0;     // 391 M-tiles

    if (fork) {
        cudaEventRecord(g_ov.eFork, 0);
        cudaStreamWaitEvent(g_ov.s2, g_ov.eFork, 0);
        cudaStreamWaitEvent(g_ov.s3, g_ov.eFork, 0);

        // CSR by dst (stream s2 — overlaps dense chain)
        k_zero_deg<<<(NN + 255) / 256, 256, 0, g_ov.s2>>>();
        k_hist    <<<(NE + 255) / 256, 256, 0, g_ov.s2>>>(ei);
        k_scan    <<<1, 1024, 0, g_ov.s2>>>();
        k_scatter <<<(NE + 255) / 256, 256, 0, g_ov.s2>>>(ei, ew);
        cudaEventRecord(g_ov.eJoin, g_ov.s2);

        // Dense chain (stream 0): prep + conv_x halves
        k_prepB1<<<(256 * 512 + 255) / 256, 256>>>(W1);
        k_prepB2<<<(128 * 256 + 255) / 256, 256>>>(Wmu, Wlv);
        k_conv_x<<<(TC0 + 255) / 256, 256>>>(x, 0, TC0);
        cudaEventRecord(g_ov.eC0, 0);
        k_conv_x<<<(TC1 + 255) / 256, 256>>>(x, TC0, TC1);
        cudaEventRecord(g_ov.eC1, 0);

        // GEMM1 halves on s3, pipelined against conv_x (tensor vs DRAM bound)
        cudaStreamWaitEvent(g_ov.s3, g_ov.eC0, 0);
        {
            dim3 g0(2, T0);
            k_mma<16, 512, 256><<<g0, 256, 0, g_ov.s3>>>(p_xh, p_B1, p_xwh, NN, 0);
        }
        cudaStreamWaitEvent(g_ov.s3, g_ov.eC1, 0);
        {
            dim3 g1(2, T1);
            k_mma<16, 512, 256><<<g1, 256, 0, g_ov.s3>>>(p_xh, p_B1, p_xwh, NN, T0);
        }
        cudaEventRecord(g_ov.eG1, g_ov.s3);

        // Join both side-chains before SPMM1
        cudaStreamWaitEvent(0, g_ov.eG1, 0);
        cudaStreamWaitEvent(0, g_ov.eJoin, 0);
    } else {
        // Fallback: fully serial on stream 0
        k_zero_deg<<<(NN + 255) / 256, 256>>>();
        k_hist    <<<(NE + 255) / 256, 256>>>(ei);
        k_scan    <<<1, 1024>>>();
        k_scatter <<<(NE + 255) / 256, 256>>>(ei, ew);
        k_prepB1<<<(256 * 512 + 255) / 256, 256>>>(W1);
        k_prepB2<<<(128 * 256 + 255) / 256, 256>>>(Wmu, Wlv);
        k_conv_x<<<(NN * 128 + 255) / 256, 256>>>(x, 0, NN * 128);
        dim3 grid(2, (NN + 127) / 128);
        k_mma<16, 512, 256><<<grid, 256>>>(p_xh, p_B1, p_xwh, NN, 0);
    }

    // SPMM1 + bias + relu (single launch, round-6 form)
    k_spmm1<<<(NN + 7) / 8, 256>>>(b1);

    // GEMM2: [mu|logvar] = h @ [Wmu|Wlv]  (K=256), in-place into g_xwh
    {
        dim3 grid(1, (NN + 127) / 128);
        k_mma<8, 256, 128><<<grid, 256>>>(p_h, p_B2, p_xwh, NN, 0);
    }

    // SPMM2 + bias -> d_out (gathers from g_xwh)
    k_spmm2<<<(NN + 7) / 8, 256>>>(bmu, blv, out);
}

// round 13
// speedup vs baseline: 1.5468x; 1.0413x over previous
#include <cuda_runtime.h>
#include <cuda_fp16.h>
#include <cstdint>

// Problem constants
#define NN 100000      // nodes
#define NE 3200000     // edges
#define NF 512         // in features
#define NH 256         // hidden
#define NL 64          // latent

// ---------------------------------------------------------------------------
// Scratch (device globals -> allocation-free, graph-capturable)
// ---------------------------------------------------------------------------
__device__ __half g_xh [(size_t)NN * NF];   // x in fp16 [NN,512]
__device__ __half g_xwh[(size_t)NN * NH];   // GEMM1 out [NN,256]; reused as GEMM2 out [NN,128]
__device__ __half g_h  [(size_t)NN * NH];   // relu(spmm1) fp16 [NN,256]
__device__ __half g_B1 [(size_t)256 * 512]; // W1^T fp16  [N=256, K=512]
__device__ __half g_B2 [(size_t)128 * 256]; // [Wmu|Wlv]^T fp16 [N=128, K=256]
__device__ int   g_off[NN + 1];
__device__ int   g_deg[NN];
__device__ int   g_cur[NN];
__device__ int2  g_edge[NE];                // .x = src, .y = bits(weight), sorted by dst

// ---------------------------------------------------------------------------
// Streams/events for graph-forked overlap (created at load time)
// ---------------------------------------------------------------------------
struct OverlapRes {
    cudaStream_t s2 = nullptr;
    cudaEvent_t  eFork = nullptr, eJoin = nullptr;
    bool ok = false;
    OverlapRes() {
        ok = (cudaStreamCreateWithFlags(&s2, cudaStreamNonBlocking) == cudaSuccess) &&
             (cudaEventCreateWithFlags(&eFork, cudaEventDisableTiming) == cudaSuccess) &&
             (cudaEventCreateWithFlags(&eJoin, cudaEventDisableTiming) == cudaSuccess);
    }
};
static OverlapRes g_ov;

// ---------------------------------------------------------------------------
// PTX helpers
// ---------------------------------------------------------------------------
__device__ __forceinline__ uint32_t smem_u32(const void* p) {
    uint32_t a;
    asm("{ .reg .u64 t; cvta.to.shared.u64 t, %1; cvt.u32.u64 %0, t; }" : "=r"(a) : "l"(p));
    return a;
}
__device__ __forceinline__ void cp16(uint32_t dst, const void* src, int sz) {
    asm volatile("cp.async.cg.shared.global [%0], [%1], 16, %2;"
                 :: "r"(dst), "l"(src), "r"(sz) : "memory");
}
__device__ __forceinline__ void cp_commit() {
    asm volatile("cp.async.commit_group;" ::: "memory");
}
template<int N> __device__ __forceinline__ void cp_wait() {
    asm volatile("cp.async.wait_group %0;" :: "n"(N) : "memory");
}

// ---------------------------------------------------------------------------
// CSR build
// ---------------------------------------------------------------------------
__global__ void k_zero_deg() {
    int i = blockIdx.x * blockDim.x + threadIdx.x;
    if (i < NN) g_deg[i] = 0;
}
__global__ void k_hist(const int* __restrict__ ei) {
    int e = blockIdx.x * blockDim.x + threadIdx.x;
    if (e < NE) atomicAdd(&g_deg[__ldg(ei + NE + e)], 1);
}
__global__ void k_scan() {
    __shared__ int wsum[32];
    int tid = threadIdx.x, lane = tid & 31, wid = tid >> 5;
    int carry = 0;
    for (int base = 0; base < NN; base += 1024) {
        int i = base + tid;
        int v = (i < NN) ? g_deg[i] : 0;
        int x = v;
        #pragma unroll
        for (int o = 1; o < 32; o <<= 1) {
            int y = __shfl_up_sync(0xffffffffu, x, o);
            if (lane >= o) x += y;
        }
        if (lane == 31) wsum[wid] = x;
        __syncthreads();
        if (wid == 0) {
            int s = wsum[lane];
            #pragma unroll
            for (int o = 1; o < 32; o <<= 1) {
                int y = __shfl_up_sync(0xffffffffu, s, o);
                if (lane >= o) s += y;
            }
            wsum[lane] = s;
        }
        __syncthreads();
        int excl = carry + x - v + (wid ? wsum[wid - 1] : 0);
        if (i < NN) { g_off[i] = excl; g_cur[i] = excl; }
        carry += wsum[31];
        __syncthreads();
    }
    if (tid == 0) g_off[NN] = carry;
}
__global__ void k_scatter(const int* __restrict__ ei, const float* __restrict__ ew) {
    int e = blockIdx.x * blockDim.x + threadIdx.x;
    if (e < NE) {
        int src = __ldg(ei + e);
        int dst = __ldg(ei + NE + e);
        float w = __ldg(ew + e);
        int pos = atomicAdd(&g_cur[dst], 1);
        g_edge[pos] = make_int2(src, __float_as_int(w));
    }
}

// ---------------------------------------------------------------------------
// fp16 prep
// ---------------------------------------------------------------------------
__global__ __launch_bounds__(256) void k_conv_x(const float* __restrict__ x) {
    int t = blockIdx.x * blockDim.x + threadIdx.x;   // one float4 -> half4
    if (t >= NN * 128) return;
    float4 v = ((const float4*)x)[t];
    __half2 h0 = __float22half2_rn(make_float2(v.x, v.y));
    __half2 h1 = __float22half2_rn(make_float2(v.z, v.w));
    ((__half2*)g_xh)[t * 2]     = h0;
    ((__half2*)g_xh)[t * 2 + 1] = h1;
}
__global__ __launch_bounds__(256) void k_prepB1(const float* __restrict__ W1) {
    int t = blockIdx.x * blockDim.x + threadIdx.x;
    if (t >= 256 * 512) return;
    int n = t >> 9, k = t & 511;
    g_B1[t] = __float2half_rn(W1[(size_t)k * 256 + n]);
}
__global__ __launch_bounds__(256) void k_prepB2(const float* __restrict__ Wmu,
                                                const float* __restrict__ Wlv) {
    int t = blockIdx.x * blockDim.x + threadIdx.x;
    if (t >= 128 * 256) return;
    int n = t >> 8, k = t & 255;
    float w = (n < 64) ? Wmu[(size_t)k * 64 + n] : Wlv[(size_t)k * 64 + (n - 64)];
    g_B2[t] = __float2half_rn(w);
}

// ---------------------------------------------------------------------------
// fp16 mma.sync GEMM: C[128x128 tile] = A @ B^T, fp16 in, f32 acc, fp16 out
//   A: [M, KA] row-major fp16; B: [N, KA] K-contig fp16; CCH chunks of K=32
// ---------------------------------------------------------------------------
template<int CCH, int KA, int LDC>
__global__ __launch_bounds__(256) void k_mma(const __half* __restrict__ A,
                                             const __half* __restrict__ B,
                                             __half* __restrict__ C, int M)
{
    constexpr int LDS = 40;
    __shared__ __align__(16) __half As[2][128 * LDS];
    __shared__ __align__(16) __half Bs[2][128 * LDS];

    int tid = threadIdx.x, lane = tid & 31, wid = tid >> 5;
    int m0 = blockIdx.y * 128, n0 = blockIdx.x * 128;
    int wm = (wid >> 2) * 64, wn = (wid & 3) * 32;

    float acc[4][4][4];
    #pragma unroll
    for (int a = 0; a < 4; a++)
        #pragma unroll
        for (int b = 0; b < 4; b++)
            #pragma unroll
            for (int q = 0; q < 4; q++) acc[a][b][q] = 0.f;

    uint32_t aBase = smem_u32(As), bBase = smem_u32(Bs);
    int r_ld = tid >> 1;
    int s0_ld = (tid & 1) * 2;

    auto load = [&](int c, int st) {
        int k0 = c * 32;
        const __half* Ap = A + (size_t)(m0 + r_ld) * KA + k0;
        const __half* Bp = B + (size_t)(n0 + r_ld) * KA + k0;
        int sz = (m0 + r_ld < M) ? 16 : 0;
        uint32_t ad = aBase + (uint32_t)(st * 128 * LDS + r_ld * LDS) * 2;
        uint32_t bd = bBase + (uint32_t)(st * 128 * LDS + r_ld * LDS) * 2;
        #pragma unroll
        for (int i = 0; i < 2; i++) {
            int s = s0_ld + i;
            cp16(ad + s * 16, Ap + s * 8, sz);
            cp16(bd + s * 16, Bp + s * 8, 16);
        }
        cp_commit();
    };

    load(0, 0);
    for (int c = 0; c < CCH; c++) {
        int st = c & 1;
        if (c + 1 < CCH) { load(c + 1, st ^ 1); cp_wait<1>(); }
        else             { cp_wait<0>(); }
        __syncthreads();

        #pragma unroll
        for (int ks = 0; ks < 2; ks++) {
            uint32_t ra[4][4], rb[4][2];
            #pragma unroll
            for (int mi = 0; mi < 4; mi++) {
                int row = wm + mi * 16 + (lane & 15);
                int col = ks * 16 + (lane >> 4) * 8;
                uint32_t ad = aBase + (uint32_t)(st * 128 * LDS + row * LDS + col) * 2;
                asm volatile("ldmatrix.sync.aligned.m8n8.x4.shared.b16 {%0,%1,%2,%3}, [%4];"
                    : "=r"(ra[mi][0]), "=r"(ra[mi][1]), "=r"(ra[mi][2]), "=r"(ra[mi][3])
                    : "r"(ad));
            }
            #pragma unroll
            for (int ni = 0; ni < 4; ni++) {
                int row = wn + ni * 8 + (lane & 7);
                int col = ks * 16 + ((lane >> 3) & 1) * 8;
                uint32_t bd = bBase + (uint32_t)(st * 128 * LDS + row * LDS + col) * 2;
                asm volatile("ldmatrix.sync.aligned.m8n8.x2.shared.b16 {%0,%1}, [%2];"
                    : "=r"(rb[ni][0]), "=r"(rb[ni][1]) : "r"(bd));
            }
            #pragma unroll
            for (int mi = 0; mi < 4; mi++)
                #pragma unroll
                for (int ni = 0; ni < 4; ni++)
                    asm volatile(
                        "mma.sync.aligned.m16n8k16.row.col.f32.f16.f16.f32 "
                        "{%0,%1,%2,%3}, {%4,%5,%6,%7}, {%8,%9}, {%0,%1,%2,%3};"
                        : "+f"(acc[mi][ni][0]), "+f"(acc[mi][ni][1]),
                          "+f"(acc[mi][ni][2]), "+f"(acc[mi][ni][3])
                        : "r"(ra[mi][0]), "r"(ra[mi][1]), "r"(ra[mi][2]), "r"(ra[mi][3]),
                          "r"(rb[ni][0]), "r"(rb[ni][1]));
        }
        __syncthreads();
    }

    #pragma unroll
    for (int mi = 0; mi < 4; mi++) {
        int r0 = m0 + wm + mi * 16 + (lane >> 2);
        #pragma unroll
        for (int ni = 0; ni < 4; ni++) {
            int cc = n0 + wn + ni * 8 + (lane & 3) * 2;
            if (r0 < M)
                *(__half2*)(C + (size_t)r0 * LDC + cc) =
                    __float22half2_rn(make_float2(acc[mi][ni][0], acc[mi][ni][1]));
            if (r0 + 8 < M)
                *(__half2*)(C + (size_t)(r0 + 8) * LDC + cc) =
                    __float22half2_rn(make_float2(acc[mi][ni][2], acc[mi][ni][3]));
        }
    }
}

// ---------------------------------------------------------------------------
// SPMM1: h = relu(A @ xwh + b1), fp16 gather (16B/lane/edge), f32 acc,
// 2x-unrolled, fp16 out; warp/row
// ---------------------------------------------------------------------------
__global__ __launch_bounds__(256) void k_spmm1(const float* __restrict__ b1) {
    int w    = (blockIdx.x * blockDim.x + threadIdx.x) >> 5;
    int lane = threadIdx.x & 31;
    if (w >= NN) return;

    int s0 = g_off[w], s1 = g_off[w + 1];
    float acc[8];
    #pragma unroll
    for (int i = 0; i < 8; i++) acc[i] = 0.f;

    auto addEdge = [&](int2 ed) {
        float we = __int_as_float(ed.y);
        uint4 v = __ldg((const uint4*)(g_xwh + (size_t)ed.x * NH) + lane);
        const __half2* hp = (const __half2*)&v;
        #pragma unroll
        for (int q = 0; q < 4; q++) {
            float2 f = __half22float2(hp[q]);
            acc[2*q]     = fmaf(we, f.x, acc[2*q]);
            acc[2*q + 1] = fmaf(we, f.y, acc[2*q + 1]);
        }
    };

    int e = s0;
    for (; e + 2 <= s1; e += 2) { addEdge(g_edge[e]); addEdge(g_edge[e + 1]); }
    if (e < s1) addEdge(g_edge[e]);

    const float4* bb = (const float4*)(b1 + lane * 8);
    float4 b0 = __ldg(bb), b1v = __ldg(bb + 1);
    acc[0] = fmaxf(acc[0] + b0.x, 0.f);  acc[1] = fmaxf(acc[1] + b0.y, 0.f);
    acc[2] = fmaxf(acc[2] + b0.z, 0.f);  acc[3] = fmaxf(acc[3] + b0.w, 0.f);
    acc[4] = fmaxf(acc[4] + b1v.x, 0.f); acc[5] = fmaxf(acc[5] + b1v.y, 0.f);
    acc[6] = fmaxf(acc[6] + b1v.z, 0.f); acc[7] = fmaxf(acc[7] + b1v.w, 0.f);

    __half2 hv[4];
    #pragma unroll
    for (int q = 0; q < 4; q++)
        hv[q] = __float22half2_rn(make_float2(acc[2*q], acc[2*q + 1]));
    *(uint4*)(g_h + (size_t)w * NH + lane * 8) = *(uint4*)hv;
}

// ---------------------------------------------------------------------------
// SPMM2: D=128 fp16 gather from g_xwh (8B/lane/edge), f32 acc, 2x unroll,
// bias, final f32 out. (g_xwh reused as GEMM2 out; serial schedule = safe.)
// ---------------------------------------------------------------------------
__global__ __launch_bounds__(256) void k_spmm2(
    const float* __restrict__ bmu, const float* __restrict__ blv,
    float* __restrict__ out)
{
    int w    = (blockIdx.x * blockDim.x + threadIdx.x) >> 5;
    int lane = threadIdx.x & 31;
    if (w >= NN) return;

    int s0 = g_off[w], s1 = g_off[w + 1];
    float acc[4] = {0.f, 0.f, 0.f, 0.f};

    auto addEdge = [&](int2 ed) {
        float we = __int_as_float(ed.y);
        uint2 v = __ldg((const uint2*)(g_xwh + (size_t)ed.x * 128) + lane);
        float2 f0 = __half22float2(*(const __half2*)&v.x);
        float2 f1 = __half22float2(*(const __half2*)&v.y);
        acc[0] = fmaf(we, f0.x, acc[0]);
        acc[1] = fmaf(we, f0.y, acc[1]);
        acc[2] = fmaf(we, f1.x, acc[2]);
        acc[3] = fmaf(we, f1.y, acc[3]);
    };

    int e = s0;
    for (; e + 2 <= s1; e += 2) { addEdge(g_edge[e]); addEdge(g_edge[e + 1]); }
    if (e < s1) addEdge(g_edge[e]);

    int col = lane * 4;
    if (col < 64) {
        float4 b = __ldg((const float4*)(bmu + col));
        *(float4*)(out + (size_t)w * 64 + col) =
            make_float4(acc[0] + b.x, acc[1] + b.y, acc[2] + b.z, acc[3] + b.w);
    } else {
        int jc = col - 64;
        float4 b = __ldg((const float4*)(blv + jc));
        *(float4*)(out + (size_t)NN * 64 + (size_t)w * 64 + jc) =
            make_float4(acc[0] + b.x, acc[1] + b.y, acc[2] + b.z, acc[3] + b.w);
    }
}

// ---------------------------------------------------------------------------
// Launch (round-6 schedule; conv_x first on the dense stream)
// ---------------------------------------------------------------------------
extern "C" void kernel_launch(void* const* d_in, const int* in_sizes, int n_in,
                              void* d_out, int out_size)
{
    const float* x   = (const float*)d_in[0];
    const int*   ei  = (const int*)  d_in[1];
    const float* ew  = (const float*)d_in[2];
    const float* W1  = (const float*)d_in[3];
    const float* b1  = (const float*)d_in[4];
    const float* Wmu = (const float*)d_in[5];
    const float* bmu = (const float*)d_in[6];
    const float* Wlv = (const float*)d_in[7];
    const float* blv = (const float*)d_in[8];
    float* out = (float*)d_out;

    __half *p_xh, *p_xwh, *p_h, *p_B1, *p_B2;
    cudaGetSymbolAddress((void**)&p_xh,  g_xh);
    cudaGetSymbolAddress((void**)&p_xwh, g_xwh);
    cudaGetSymbolAddress((void**)&p_h,   g_h);
    cudaGetSymbolAddress((void**)&p_B1,  g_B1);
    cudaGetSymbolAddress((void**)&p_B2,  g_B2);

    bool fork = g_ov.ok;
    cudaStream_t sC = fork ? g_ov.s2 : (cudaStream_t)0;

    if (fork) {
        cudaEventRecord(g_ov.eFork, 0);
        cudaStreamWaitEvent(g_ov.s2, g_ov.eFork, 0);
    }

    // CSR by dst (stream sC — overlaps dense chain)
    k_zero_deg<<<(NN + 255) / 256, 256, 0, sC>>>();
    k_hist    <<<(NE + 255) / 256, 256, 0, sC>>>(ei);
    k_scan    <<<1, 1024, 0, sC>>>();
    k_scatter <<<(NE + 255) / 256, 256, 0, sC>>>(ei, ew);
    if (fork) cudaEventRecord(g_ov.eJoin, g_ov.s2);

    // Dense chain (stream 0): conv first (wide kernel starts immediately),
    // then tiny weight preps, then GEMM1
    k_conv_x<<<(NN * 128 + 255) / 256, 256>>>(x);
    k_prepB1<<<(256 * 512 + 255) / 256, 256>>>(W1);
    k_prepB2<<<(128 * 256 + 255) / 256, 256>>>(Wmu, Wlv);
    {
        dim3 grid(2, (NN + 127) / 128);
        k_mma<16, 512, 256><<<grid, 256>>>(p_xh, p_B1, p_xwh, NN);
    }

    if (fork) cudaStreamWaitEvent(0, g_ov.eJoin, 0);

    // SPMM1 + bias + relu
    k_spmm1<<<(NN + 7) / 8, 256>>>(b1);

    // GEMM2: [mu|logvar] = h @ [Wmu|Wlv]  (K=256), in-place into g_xwh
    {
        dim3 grid(1, (NN + 127) / 128);
        k_mma<8, 256, 128><<<grid, 256>>>(p_h, p_B2, p_xwh, NN);
    }

    // SPMM2 + bias -> d_out
    k_spmm2<<<(NN + 7) / 8, 256>>>(bmu, blv, out);
}